// round 5
// baseline (speedup 1.0000x reference)
#include <cuda_runtime.h>
#include <math.h>
#include <stdint.h>

// ---- problem constants ----
#define Bg   64
#define Nn   1024
#define Dd   128
#define EPG  8192
#define NTOT (Bg*Nn)      // 65536
#define ETOT (Bg*EPG)     // 524288
#define KP   820          // kept nodes per graph
#define BK   (Bg*KP)      // 52480
#define NEGS 0.2f
#define LAMBDA 1.0f
#define TJ   8            // columns per sparsemax tile
#define SHP  9            // shared pitch (bank-conflict free)
#define NQ   26           // ceil(KP/32)

// ---- device scratch ----
__device__ int    g_cnt_out[NTOT];
__device__ int    g_cnt_in[NTOT];
__device__ float  g_sn[NTOT];
__device__ float  g_dn[NTOT];
__device__ int    g_off[NTOT];
__device__ int    g_cur[NTOT];
__device__ int    g_csr_src[ETOT];
__device__ float  g_csr_val[ETOT];
__device__ double g_wa_d[Dd];
__device__ float  g_score[NTOT];
__device__ int    g_mask[NTOT];
__device__ float  g_wsrc[BK];
__device__ float  g_wdst[BK];
__device__ int    g_pnode[BK];
__device__ int    g_cnt2[BK];
__device__ int    g_off2[BK];
__device__ int    g_cur2[BK];
__device__ int    g2_row[ETOT];
__device__ float  g2_val[ETOT];

// XLA f32 tanh (Eigen rational approximation, as emitted by XLA's elemental IR)
__device__ __forceinline__ float tanh_xla(float x) {
    float ax = fabsf(x);
    float cx = fminf(fmaxf(x, -7.90531110763549805f), 7.90531110763549805f);
    float x2 = cx * cx;
    float p = fmaf(x2, -2.76076847742355e-16f, 2.00018790482477e-13f);
    p = fmaf(p, x2, -8.60467152213735e-11f);
    p = fmaf(p, x2, 5.12229709037114e-08f);
    p = fmaf(p, x2, 1.48572235717979e-05f);
    p = fmaf(p, x2, 6.37261928875436e-04f);
    p = fmaf(p, x2, 4.89352455891786e-03f);
    p = p * cx;
    float q = fmaf(x2, 1.19825839466702e-06f, 1.18534705686654e-04f);
    q = fmaf(q, x2, 2.26843463243900e-03f);
    q = fmaf(q, x2, 4.89352518554385e-03f);
    float r = p / q;
    return (ax < 0.0004f) ? x : r;
}

__global__ void __launch_bounds__(256) k_init() {
    int i = blockIdx.x * blockDim.x + threadIdx.x;
    if (i < NTOT) { g_cnt_out[i] = 0; g_cnt_in[i] = 0; g_cur[i] = 0; g_mask[i] = -1; }
    if (i < BK)   { g_cnt2[i] = 0; g_cur2[i] = 0; }
}

__global__ void __launch_bounds__(256) k_count(const int* __restrict__ src,
                                               const int* __restrict__ dst) {
    int e = blockIdx.x * blockDim.x + threadIdx.x;
    if (e < ETOT) {
        atomicAdd(&g_cnt_out[src[e]], 1);
        atomicAdd(&g_cnt_in[dst[e]], 1);
    }
}

// correctly-rounded deg^-0.5 in f32 (via double)
__global__ void __launch_bounds__(256) k_deg() {
    int i = blockIdx.x * blockDim.x + threadIdx.x;
    if (i < NTOT) {
        double od = (double)max(g_cnt_out[i], 1);
        double id = (double)max(g_cnt_in[i], 1);
        g_sn[i] = (float)(1.0 / sqrt(od));
        g_dn[i] = (float)(1.0 / sqrt(id));
    }
}

__device__ __forceinline__ void scan_impl(const int* __restrict__ cnt,
                                          int* __restrict__ off, int n) {
    __shared__ int ss[1024];
    int tid = threadIdx.x;
    int per = (n + 1023) >> 10;
    int s0 = tid * per;
    int s = 0;
    for (int i = 0; i < per; i++) { int x = s0 + i; if (x < n) s += cnt[x]; }
    ss[tid] = s; __syncthreads();
    for (int d = 1; d < 1024; d <<= 1) {
        int v = (tid >= d) ? ss[tid - d] : 0;
        __syncthreads();
        ss[tid] += v;
        __syncthreads();
    }
    int run = (tid > 0) ? ss[tid - 1] : 0;
    for (int i = 0; i < per; i++) {
        int x = s0 + i;
        if (x < n) { off[x] = run; run += cnt[x]; }
    }
}
__global__ void __launch_bounds__(1024) k_scan1() { scan_impl(g_cnt_in, g_off, NTOT); }
__global__ void __launch_bounds__(1024) k_scan2() { scan_impl(g_cnt2, g_off2, BK); }

__global__ void __launch_bounds__(256) k_scatter1(const int* __restrict__ src,
                                                  const int* __restrict__ dst,
                                                  const float* __restrict__ ef) {
    int e = blockIdx.x * blockDim.x + threadIdx.x;
    if (e < ETOT) {
        int dn = dst[e], sn = src[e];
        int pos = g_off[dn] + atomicAdd(&g_cur[dn], 1);
        g_csr_src[pos] = sn;
        g_csr_val[pos] = (sn != dn) ? ef[e] : 0.0f;  // e_feat * nonself
    }
}

// wa = W @ a in double (canonical)
__global__ void __launch_bounds__(Dd) k_wa(const float* __restrict__ W,
                                           const float* __restrict__ a) {
    int j = threadIdx.x;
    double s = 0.0;
    for (int k = 0; k < Dd; k++) s += (double)W[j * Dd + k] * (double)a[k];
    g_wa_d[j] = s;
}

// fused: neighbor agg (double accum) + info in XLA row-reduce order + XLA sigmoid gate
// XLA GPU row reduction (vector=2, one warp/row): lane L owns elements
// {2L, 2L+1} then {64+2L, 65+2L}, accumulated sequentially in f32, then a
// 5-step shfl_down butterfly (16,8,4,2,1); result in lane 0.
__global__ void __launch_bounds__(256) k_node(const float* __restrict__ feat,
                                              float* __restrict__ out_xs) {
    int gw = (blockIdx.x * blockDim.x + threadIdx.x) >> 5;
    int lane = threadIdx.x & 31;
    if (gw >= NTOT) return;
    int node = gw;
    const float2* frow_a = (const float2*)(feat + (size_t)node * Dd);        // elems 2L,2L+1
    const float2* frow_b = (const float2*)(feat + (size_t)node * Dd + 64);   // elems 64+2L,65+2L
    float2 fva = frow_a[lane];
    float2 fvb = frow_b[lane];
    double a0 = 0.0, a1 = 0.0, a2 = 0.0, a3 = 0.0;
    int st = g_off[node], en = st + g_cnt_in[node];
    for (int p = st; p < en; p++) {
        float v = g_csr_val[p];
        if (v != 0.f) {
            int s = g_csr_src[p];
            float sn = g_sn[s];
            float2 fsa = ((const float2*)(feat + (size_t)s * Dd))[lane];
            float2 fsb = ((const float2*)(feat + (size_t)s * Dd + 64))[lane];
            // elementwise f32 exactly like ref: (feat*sn) then * e_feat
            a0 += (double)((fsa.x * sn) * v);
            a1 += (double)((fsa.y * sn) * v);
            a2 += (double)((fsb.x * sn) * v);
            a3 += (double)((fsb.y * sn) * v);
        }
    }
    float dnf = g_dn[node];
    float g0 = (float)a0, g1 = (float)a1, g2v = (float)a2, g3 = (float)a3;
    // f32 elementwise chain like ref, then f32 accumulation in XLA thread order
    float t0 = fabsf(fva.x - g0 * dnf);
    float t1 = fabsf(fva.y - g1 * dnf);
    float t2 = fabsf(fvb.x - g2v * dnf);
    float t3 = fabsf(fvb.y - g3 * dnf);
    float acc = ((t0 + t1) + t2) + t3;
    #pragma unroll
    for (int o = 16; o; o >>= 1)
        acc += __shfl_down_sync(0xffffffffu, acc, o);
    // attn dot in double (canonical; cuBLAS order unknowable)
    double dp_d = (double)fva.x * g_wa_d[2 * lane + 0]
                + (double)fva.y * g_wa_d[2 * lane + 1]
                + (double)fvb.x * g_wa_d[64 + 2 * lane + 0]
                + (double)fvb.y * g_wa_d[64 + 2 * lane + 1];
    #pragma unroll
    for (int o = 16; o; o >>= 1)
        dp_d += __shfl_xor_sync(0xffffffffu, dp_d, o);
    if (lane == 0) {
        float lr = (float)dp_d;
        float ll = (lr >= 0.f) ? lr : NEGS * lr;        // leaky_relu 0.2 (f32)
        float t = tanh_xla(0.5f * ll);                  // XLA logistic = 0.5+0.5*tanh(0.5x)
        float attn = 0.5f * t + 0.5f;
        float sc = acc * attn;                          // final f32 multiply like ref
        g_score[node] = sc;
        out_xs[node] = sc;
    }
}

// per-graph top-K via bitonic 1024 (desc by score, ties asc by index)
__global__ void __launch_bounds__(1024) k_topk(float* __restrict__ out_perm) {
    __shared__ float skey[Nn];
    __shared__ int   sidx[Nn];
    int b = blockIdx.x, tid = threadIdx.x;
    skey[tid] = g_score[b * Nn + tid];
    sidx[tid] = tid;
    __syncthreads();
    for (int k = 2; k <= Nn; k <<= 1) {
        for (int j = k >> 1; j > 0; j >>= 1) {
            int i = tid, ixj = i ^ j;
            if (ixj > i) {
                float ka = skey[i], kb = skey[ixj];
                int ia = sidx[i], ib = sidx[ixj];
                bool up = ((i & k) == 0);
                bool bBeforeA = (kb > ka) || (kb == ka && ib < ia);
                bool aBeforeB = (ka > kb) || (ka == kb && ia < ib);
                bool sw = up ? bBeforeA : aBeforeB;
                if (sw) { skey[i] = kb; skey[ixj] = ka; sidx[i] = ib; sidx[ixj] = ia; }
            }
            __syncthreads();
        }
    }
    if (tid < KP) {
        int node = b * Nn + sidx[tid];
        int p = b * KP + tid;
        g_pnode[p] = node;
        g_mask[node] = p;
        out_perm[p] = (float)node;
    }
}

__global__ void __launch_bounds__(256) k_cnt2(const int* __restrict__ src,
                                              const int* __restrict__ dst) {
    int e = blockIdx.x * blockDim.x + threadIdx.x;
    if (e < ETOT) {
        int nr = g_mask[src[e]], nc = g_mask[dst[e]];
        if (nr >= 0 && nc >= 0) atomicAdd(&g_cnt2[nc], 1);
    }
}
__global__ void __launch_bounds__(256) k_scatter2(const int* __restrict__ src,
                                                  const int* __restrict__ dst,
                                                  const float* __restrict__ ef) {
    int e = blockIdx.x * blockDim.x + threadIdx.x;
    if (e < ETOT) {
        int nr = g_mask[src[e]], nc = g_mask[dst[e]];
        if (nr >= 0 && nc >= 0) {
            int pos = g_off2[nc] + atomicAdd(&g_cur2[nc], 1);
            g2_row[pos] = nr % KP;
            g2_val[pos] = LAMBDA * ef[e];
        }
    }
}

__global__ void __launch_bounds__(256) k_pool(const float* __restrict__ feat,
                                              const float* __restrict__ att,
                                              float* __restrict__ out_fp) {
    int p = (blockIdx.x * blockDim.x + threadIdx.x) >> 5;
    int lane = threadIdx.x & 31;
    if (p >= BK) return;
    int node = g_pnode[p];
    float4 fv = ((const float4*)(feat + (size_t)node * Dd))[lane];
    ((float4*)(out_fp + (size_t)p * Dd))[lane] = fv;
    float4 a1 = ((const float4*)att)[lane];
    float4 a2 = ((const float4*)(att + Dd))[lane];
    double s1 = (double)fv.x * a1.x + (double)fv.y * a1.y
              + (double)fv.z * a1.z + (double)fv.w * a1.w;
    double s2 = (double)fv.x * a2.x + (double)fv.y * a2.y
              + (double)fv.z * a2.z + (double)fv.w * a2.w;
    for (int o = 16; o; o >>= 1) {
        s1 += __shfl_xor_sync(0xffffffffu, s1, o);
        s2 += __shfl_xor_sync(0xffffffffu, s2, o);
    }
    if (lane == 0) { g_wsrc[p] = (float)s1; g_wdst[p] = (float)s2; }
}

// fused Wblk build + edge adds + sparsemax (Michelot, double tau) + transposed write
__global__ void __launch_bounds__(256) k_spm(float* __restrict__ out_w) {
    __shared__ float sh[KP * SHP];
    int b = blockIdx.y;
    int j0 = blockIdx.x * TJ;
    int ncols = KP - j0; if (ncols > TJ) ncols = TJ;
    int t = threadIdx.x;
    int w = t & (TJ - 1), iq = t >> 3;
    int wp = t >> 5, lane = t & 31;

    if (w < ncols) {
        float wdj = g_wdst[(size_t)b * KP + j0 + w];
        for (int i = iq; i < KP; i += 32) {
            float v = g_wsrc[b * KP + i] + wdj;
            sh[i * SHP + w] = (v >= 0.f) ? v : NEGS * v;
        }
    }
    __syncthreads();

    if (wp < ncols) {
        int c = b * KP + j0 + wp;
        int st = g_off2[c], en = st + g_cnt2[c];
        for (int e = st + lane; e < en; e += 32)
            atomicAdd(&sh[g2_row[e] * SHP + wp], g2_val[e]);
    }
    __syncthreads();

    if (wp < ncols) {
        float z[NQ];
        #pragma unroll
        for (int q = 0; q < NQ; q++) {
            int i = q * 32 + lane;
            z[q] = (i < KP) ? sh[i * SHP + wp] : -1e30f;
        }
        double s = 0.0;
        #pragma unroll
        for (int q = 0; q < NQ; q++) { int i = q * 32 + lane; if (i < KP) s += (double)z[q]; }
        for (int o = 16; o; o >>= 1) s += __shfl_xor_sync(0xffffffffu, s, o);
        double tau = (s - 1.0) / (double)KP;
        int kprev = KP;
        for (int it = 0; it < 200; it++) {
            double s2 = 0.0; int k2 = 0;
            #pragma unroll
            for (int q = 0; q < NQ; q++) {
                double zz = (double)z[q];
                if (zz > tau) { s2 += zz; k2++; }
            }
            for (int o = 16; o; o >>= 1) {
                s2 += __shfl_xor_sync(0xffffffffu, s2, o);
                k2 += __shfl_xor_sync(0xffffffffu, k2, o);
            }
            if (k2 == kprev) break;
            tau = (s2 - 1.0) / (double)k2;
            kprev = k2;
        }
        float tauf = (float)tau;
        #pragma unroll
        for (int q = 0; q < NQ; q++) {
            int i = q * 32 + lane;
            if (i < KP) {
                float d = z[q] - tauf;
                sh[i * SHP + wp] = (d > 1e-9f) ? d : 0.f;
            }
        }
    }
    __syncthreads();

    {
        size_t base = (size_t)b * KP * KP;
        int j = j0 + w;
        if (j < KP && w < ncols) {
            for (int i = iq; i < KP; i += 32)
                out_w[base + (size_t)i * KP + j] = sh[i * SHP + w];
        }
    }
}

extern "C" void kernel_launch(void* const* d_in, const int* in_sizes, int n_in,
                              void* d_out, int out_size) {
    const float* feat = (const float*)d_in[0];
    const float* ef   = (const float*)d_in[1];
    const float* W    = (const float*)d_in[2];
    const float* a    = (const float*)d_in[3];
    const float* att  = (const float*)d_in[4];
    const int*   src  = (const int*)d_in[5];
    const int*   dst  = (const int*)d_in[6];

    float* out      = (float*)d_out;
    float* out_fp   = out;                               // [BK, D]
    float* out_w    = out + (size_t)BK * Dd;             // [B, KP, KP]
    float* out_perm = out_w + (size_t)BK * KP;           // [BK]
    float* out_xs   = out_perm + BK;                     // [NTOT]

    k_init<<<(NTOT + 255) / 256, 256>>>();
    k_count<<<(ETOT + 255) / 256, 256>>>(src, dst);
    k_deg<<<(NTOT + 255) / 256, 256>>>();
    k_scan1<<<1, 1024>>>();
    k_scatter1<<<(ETOT + 255) / 256, 256>>>(src, dst, ef);
    k_wa<<<1, Dd>>>(W, a);
    k_node<<<(NTOT * 32 + 255) / 256, 256>>>(feat, out_xs);
    k_topk<<<Bg, 1024>>>(out_perm);
    k_cnt2<<<(ETOT + 255) / 256, 256>>>(src, dst);
    k_scan2<<<1, 1024>>>();
    k_scatter2<<<(ETOT + 255) / 256, 256>>>(src, dst, ef);
    k_pool<<<(BK * 32 + 255) / 256, 256>>>(feat, att, out_fp);

    dim3 g((KP + TJ - 1) / TJ, Bg);
    k_spm<<<g, 256>>>(out_w);
}

// round 6
// speedup vs baseline: 4.7919x; 4.7919x over previous
#include <cuda_runtime.h>
#include <math.h>
#include <stdint.h>

// ---- problem constants ----
#define Bg   64
#define Nn   1024
#define Dd   128
#define EPG  8192
#define NTOT (Bg*Nn)      // 65536
#define ETOT (Bg*EPG)     // 524288
#define KP   820          // kept nodes per graph
#define BK   (Bg*KP)      // 52480
#define NEGS 0.2f
#define LAMBDA 1.0f
#define TJ   8            // columns per sparsemax tile
#define SHP  9            // shared pitch (bank-conflict free)
#define NQ   26           // ceil(KP/32)
#define CAP  64           // bucket capacity (P(deg>=48) ~ 5e-15)

// ---- device scratch ----
__device__ int    g_cnt_out[NTOT];
__device__ int    g_cnt_in[NTOT];
__device__ float  g_sn[NTOT];
__device__ float  g_dn[NTOT];
__device__ int    g_csr_src[NTOT * CAP];
__device__ float  g_csr_val[NTOT * CAP];
__device__ double g_wa_d[Dd];
__device__ float  g_score[NTOT];
__device__ int    g_mask[NTOT];
__device__ float  g_wsrc[BK];
__device__ float  g_wdst[BK];
__device__ int    g_pnode[BK];
__device__ int    g_cnt2[BK];
__device__ int    g2_row[BK * CAP];
__device__ float  g2_val[BK * CAP];

// XLA f32 tanh (Eigen rational approximation, as emitted by XLA's elemental IR)
__device__ __forceinline__ float tanh_xla(float x) {
    float ax = fabsf(x);
    float cx = fminf(fmaxf(x, -7.90531110763549805f), 7.90531110763549805f);
    float x2 = cx * cx;
    float p = fmaf(x2, -2.76076847742355e-16f, 2.00018790482477e-13f);
    p = fmaf(p, x2, -8.60467152213735e-11f);
    p = fmaf(p, x2, 5.12229709037114e-08f);
    p = fmaf(p, x2, 1.48572235717979e-05f);
    p = fmaf(p, x2, 6.37261928875436e-04f);
    p = fmaf(p, x2, 4.89352455891786e-03f);
    p = p * cx;
    float q = fmaf(x2, 1.19825839466702e-06f, 1.18534705686654e-04f);
    q = fmaf(q, x2, 2.26843463243900e-03f);
    q = fmaf(q, x2, 4.89352518554385e-03f);
    float r = p / q;
    return (ax < 0.0004f) ? x : r;
}

__global__ void __launch_bounds__(256) k_init() {
    int i = blockIdx.x * blockDim.x + threadIdx.x;
    if (i < NTOT) { g_cnt_out[i] = 0; g_cnt_in[i] = 0; g_mask[i] = -1; }
    if (i < BK)   { g_cnt2[i] = 0; }
}

// fused degree count + direct-bucket CSR-by-dst scatter
__global__ void __launch_bounds__(256) k_scatter1(const int* __restrict__ src,
                                                  const int* __restrict__ dst,
                                                  const float* __restrict__ ef) {
    int e = blockIdx.x * blockDim.x + threadIdx.x;
    if (e < ETOT) {
        int dn = dst[e], sn = src[e];
        atomicAdd(&g_cnt_out[sn], 1);
        int slot = atomicAdd(&g_cnt_in[dn], 1);
        if (slot < CAP) {
            g_csr_src[dn * CAP + slot] = sn;
            g_csr_val[dn * CAP + slot] = (sn != dn) ? ef[e] : 0.0f;  // e_feat*nonself
        }
    }
}

// correctly-rounded deg^-0.5 in f32 (via double)
__global__ void __launch_bounds__(256) k_deg() {
    int i = blockIdx.x * blockDim.x + threadIdx.x;
    if (i < NTOT) {
        double od = (double)max(g_cnt_out[i], 1);
        double id = (double)max(g_cnt_in[i], 1);
        g_sn[i] = (float)(1.0 / sqrt(od));
        g_dn[i] = (float)(1.0 / sqrt(id));
    }
}

// wa = W @ a in double (canonical)
__global__ void __launch_bounds__(Dd) k_wa(const float* __restrict__ W,
                                           const float* __restrict__ a) {
    int j = threadIdx.x;
    double s = 0.0;
    for (int k = 0; k < Dd; k++) s += (double)W[j * Dd + k] * (double)a[k];
    g_wa_d[j] = s;
}

// fused: neighbor agg (double accum) + info in XLA row-reduce order + XLA sigmoid gate
__global__ void __launch_bounds__(256) k_node(const float* __restrict__ feat,
                                              float* __restrict__ out_xs) {
    int gw = (blockIdx.x * blockDim.x + threadIdx.x) >> 5;
    int lane = threadIdx.x & 31;
    if (gw >= NTOT) return;
    int node = gw;
    float2 fva = ((const float2*)(feat + (size_t)node * Dd))[lane];
    float2 fvb = ((const float2*)(feat + (size_t)node * Dd + 64))[lane];
    double a0 = 0.0, a1 = 0.0, a2 = 0.0, a3 = 0.0;
    int cnt = g_cnt_in[node]; if (cnt > CAP) cnt = CAP;
    int base = node * CAP;
    for (int p = 0; p < cnt; p++) {
        float v = g_csr_val[base + p];
        if (v != 0.f) {
            int s = g_csr_src[base + p];
            float sn = g_sn[s];
            float2 fsa = ((const float2*)(feat + (size_t)s * Dd))[lane];
            float2 fsb = ((const float2*)(feat + (size_t)s * Dd + 64))[lane];
            a0 += (double)((fsa.x * sn) * v);
            a1 += (double)((fsa.y * sn) * v);
            a2 += (double)((fsb.x * sn) * v);
            a3 += (double)((fsb.y * sn) * v);
        }
    }
    float dnf = g_dn[node];
    float g0 = (float)a0, g1 = (float)a1, g2v = (float)a2, g3 = (float)a3;
    float t0 = fabsf(fva.x - g0 * dnf);
    float t1 = fabsf(fva.y - g1 * dnf);
    float t2 = fabsf(fvb.x - g2v * dnf);
    float t3 = fabsf(fvb.y - g3 * dnf);
    float acc = ((t0 + t1) + t2) + t3;
    #pragma unroll
    for (int o = 16; o; o >>= 1)
        acc += __shfl_down_sync(0xffffffffu, acc, o);
    double dp_d = (double)fva.x * g_wa_d[2 * lane + 0]
                + (double)fva.y * g_wa_d[2 * lane + 1]
                + (double)fvb.x * g_wa_d[64 + 2 * lane + 0]
                + (double)fvb.y * g_wa_d[64 + 2 * lane + 1];
    #pragma unroll
    for (int o = 16; o; o >>= 1)
        dp_d += __shfl_xor_sync(0xffffffffu, dp_d, o);
    if (lane == 0) {
        float lr = (float)dp_d;
        float ll = (lr >= 0.f) ? lr : NEGS * lr;
        float t = tanh_xla(0.5f * ll);
        float attn = 0.5f * t + 0.5f;
        float sc = acc * attn;
        g_score[node] = sc;
        out_xs[node] = sc;
    }
}

// per-graph top-K via bitonic 1024 (desc by score, ties asc by index)
__global__ void __launch_bounds__(1024) k_topk(float* __restrict__ out_perm) {
    __shared__ float skey[Nn];
    __shared__ int   sidx[Nn];
    int b = blockIdx.x, tid = threadIdx.x;
    skey[tid] = g_score[b * Nn + tid];
    sidx[tid] = tid;
    __syncthreads();
    for (int k = 2; k <= Nn; k <<= 1) {
        for (int j = k >> 1; j > 0; j >>= 1) {
            int i = tid, ixj = i ^ j;
            if (ixj > i) {
                float ka = skey[i], kb = skey[ixj];
                int ia = sidx[i], ib = sidx[ixj];
                bool up = ((i & k) == 0);
                bool bBeforeA = (kb > ka) || (kb == ka && ib < ia);
                bool aBeforeB = (ka > kb) || (ka == kb && ia < ib);
                bool sw = up ? bBeforeA : aBeforeB;
                if (sw) { skey[i] = kb; skey[ixj] = ka; sidx[i] = ib; sidx[ixj] = ia; }
            }
            __syncthreads();
        }
    }
    if (tid < KP) {
        int node = b * Nn + sidx[tid];
        int p = b * KP + tid;
        g_pnode[p] = node;
        g_mask[node] = p;
        out_perm[p] = (float)node;
    }
}

// direct-bucket CSR of valid pooled edges, grouped by pooled column
__global__ void __launch_bounds__(256) k_scatter2(const int* __restrict__ src,
                                                  const int* __restrict__ dst,
                                                  const float* __restrict__ ef) {
    int e = blockIdx.x * blockDim.x + threadIdx.x;
    if (e < ETOT) {
        int nr = g_mask[src[e]], nc = g_mask[dst[e]];
        if (nr >= 0 && nc >= 0) {
            int slot = atomicAdd(&g_cnt2[nc], 1);
            if (slot < CAP) {
                g2_row[nc * CAP + slot] = nr % KP;
                g2_val[nc * CAP + slot] = LAMBDA * ef[e];
            }
        }
    }
}

__global__ void __launch_bounds__(256) k_pool(const float* __restrict__ feat,
                                              const float* __restrict__ att,
                                              float* __restrict__ out_fp) {
    int p = (blockIdx.x * blockDim.x + threadIdx.x) >> 5;
    int lane = threadIdx.x & 31;
    if (p >= BK) return;
    int node = g_pnode[p];
    float4 fv = ((const float4*)(feat + (size_t)node * Dd))[lane];
    ((float4*)(out_fp + (size_t)p * Dd))[lane] = fv;
    float4 a1 = ((const float4*)att)[lane];
    float4 a2 = ((const float4*)(att + Dd))[lane];
    double s1 = (double)fv.x * a1.x + (double)fv.y * a1.y
              + (double)fv.z * a1.z + (double)fv.w * a1.w;
    double s2 = (double)fv.x * a2.x + (double)fv.y * a2.y
              + (double)fv.z * a2.z + (double)fv.w * a2.w;
    for (int o = 16; o; o >>= 1) {
        s1 += __shfl_xor_sync(0xffffffffu, s1, o);
        s2 += __shfl_xor_sync(0xffffffffu, s2, o);
    }
    if (lane == 0) { g_wsrc[p] = (float)s1; g_wdst[p] = (float)s2; }
}

// fused Wblk build + edge adds + sparsemax (Michelot, f32) + transposed write
__global__ void __launch_bounds__(256) k_spm(float* __restrict__ out_w) {
    __shared__ float sh[KP * SHP];
    int b = blockIdx.y;
    int j0 = blockIdx.x * TJ;
    int ncols = KP - j0; if (ncols > TJ) ncols = TJ;
    int t = threadIdx.x;
    int w = t & (TJ - 1), iq = t >> 3;
    int wp = t >> 5, lane = t & 31;

    // phase 1: base scores leakyrelu(wsrc[i] + wdst[j])
    if (w < ncols) {
        float wdj = g_wdst[(size_t)b * KP + j0 + w];
        for (int i = iq; i < KP; i += 32) {
            float v = g_wsrc[b * KP + i] + wdj;
            sh[i * SHP + w] = (v >= 0.f) ? v : NEGS * v;
        }
    }
    __syncthreads();

    // phase 2: sparse edge additions (duplicates accumulate)
    if (wp < ncols) {
        int c = b * KP + j0 + wp;
        int cnt = g_cnt2[c]; if (cnt > CAP) cnt = CAP;
        int base = c * CAP;
        for (int e = lane; e < cnt; e += 32)
            atomicAdd(&sh[g2_row[base + e] * SHP + wp], g2_val[base + e]);
    }
    __syncthreads();

    // phase 3: sparsemax per column via Michelot (f32)
    if (wp < ncols) {
        float z[NQ];
        #pragma unroll
        for (int q = 0; q < NQ; q++) {
            int i = q * 32 + lane;
            z[q] = (i < KP) ? sh[i * SHP + wp] : -1e30f;
        }
        float s = 0.f;
        #pragma unroll
        for (int q = 0; q < NQ; q++) { int i = q * 32 + lane; if (i < KP) s += z[q]; }
        #pragma unroll
        for (int o = 16; o; o >>= 1) s += __shfl_xor_sync(0xffffffffu, s, o);
        float tau = (s - 1.f) / (float)KP;
        int kprev = KP;
        for (int it = 0; it < 100; it++) {
            float s2 = 0.f; int k2 = 0;
            #pragma unroll
            for (int q = 0; q < NQ; q++) {
                float zz = z[q];
                if (zz > tau) { s2 += zz; k2++; }
            }
            #pragma unroll
            for (int o = 16; o; o >>= 1) {
                s2 += __shfl_xor_sync(0xffffffffu, s2, o);
                k2 += __shfl_xor_sync(0xffffffffu, k2, o);
            }
            if (k2 == kprev || k2 == 0) break;
            tau = (s2 - 1.f) / (float)k2;
            kprev = k2;
        }
        #pragma unroll
        for (int q = 0; q < NQ; q++) {
            int i = q * 32 + lane;
            if (i < KP) {
                float d = z[q] - tau;
                sh[i * SHP + wp] = (d > 1e-9f) ? d : 0.f;
            }
        }
    }
    __syncthreads();

    // phase 4: coalesced transposed write: out[b][i][j]
    {
        size_t base = (size_t)b * KP * KP;
        int j = j0 + w;
        if (j < KP && w < ncols) {
            for (int i = iq; i < KP; i += 32)
                out_w[base + (size_t)i * KP + j] = sh[i * SHP + w];
        }
    }
}

extern "C" void kernel_launch(void* const* d_in, const int* in_sizes, int n_in,
                              void* d_out, int out_size) {
    const float* feat = (const float*)d_in[0];
    const float* ef   = (const float*)d_in[1];
    const float* W    = (const float*)d_in[2];
    const float* a    = (const float*)d_in[3];
    const float* att  = (const float*)d_in[4];
    const int*   src  = (const int*)d_in[5];
    const int*   dst  = (const int*)d_in[6];

    float* out      = (float*)d_out;
    float* out_fp   = out;                               // [BK, D]
    float* out_w    = out + (size_t)BK * Dd;             // [B, KP, KP]
    float* out_perm = out_w + (size_t)BK * KP;           // [BK]
    float* out_xs   = out_perm + BK;                     // [NTOT]

    k_init<<<(NTOT + 255) / 256, 256>>>();
    k_scatter1<<<(ETOT + 255) / 256, 256>>>(src, dst, ef);
    k_deg<<<(NTOT + 255) / 256, 256>>>();
    k_wa<<<1, Dd>>>(W, a);
    k_node<<<(NTOT * 32 + 255) / 256, 256>>>(feat, out_xs);
    k_topk<<<Bg, 1024>>>(out_perm);
    k_scatter2<<<(ETOT + 255) / 256, 256>>>(src, dst, ef);
    k_pool<<<(BK * 32 + 255) / 256, 256>>>(feat, att, out_fp);

    dim3 g((KP + TJ - 1) / TJ, Bg);
    k_spm<<<g, 256>>>(out_w);
}

// round 7
// speedup vs baseline: 5.0589x; 1.0557x over previous
#include <cuda_runtime.h>
#include <math.h>
#include <stdint.h>

// ---- problem constants ----
#define Bg   64
#define Nn   1024
#define Dd   128
#define EPG  8192
#define NTOT (Bg*Nn)      // 65536
#define ETOT (Bg*EPG)     // 524288
#define KP   820          // kept nodes per graph
#define BK   (Bg*KP)      // 52480
#define NEGS 0.2f
#define LAMBDA 1.0f
#define TJ   8            // columns per sparsemax tile
#define SHP  9            // shared pitch (bank-conflict free)
#define NQ   26           // ceil(KP/32)
#define CAP  64           // bucket capacity (P(deg>=48) ~ 5e-15)

// ---- device scratch ----
__device__ int    g_cnt_out[NTOT];
__device__ int    g_cnt_in[NTOT];
__device__ float  g_sn[NTOT];
__device__ float  g_dn[NTOT];
__device__ int    g_csr_src[NTOT * CAP];
__device__ float  g_csr_val[NTOT * CAP];
__device__ double g_wa_d[Dd];
__device__ float  g_score[NTOT];
__device__ int    g_mask[NTOT];
__device__ float  g_wsrc[BK];
__device__ float  g_wdst[BK];
__device__ int    g_pnode[BK];
__device__ int    g_cnt2[BK];
__device__ int    g2_row[BK * CAP];
__device__ float  g2_val[BK * CAP];

// XLA f32 tanh (Eigen rational approximation, as emitted by XLA's elemental IR)
__device__ __forceinline__ float tanh_xla(float x) {
    float ax = fabsf(x);
    float cx = fminf(fmaxf(x, -7.90531110763549805f), 7.90531110763549805f);
    float x2 = cx * cx;
    float p = fmaf(x2, -2.76076847742355e-16f, 2.00018790482477e-13f);
    p = fmaf(p, x2, -8.60467152213735e-11f);
    p = fmaf(p, x2, 5.12229709037114e-08f);
    p = fmaf(p, x2, 1.48572235717979e-05f);
    p = fmaf(p, x2, 6.37261928875436e-04f);
    p = fmaf(p, x2, 4.89352455891786e-03f);
    p = p * cx;
    float q = fmaf(x2, 1.19825839466702e-06f, 1.18534705686654e-04f);
    q = fmaf(q, x2, 2.26843463243900e-03f);
    q = fmaf(q, x2, 4.89352518554385e-03f);
    float r = p / q;
    return (ax < 0.0004f) ? x : r;
}

__global__ void __launch_bounds__(256) k_init() {
    int i = blockIdx.x * blockDim.x + threadIdx.x;
    if (i < NTOT) { g_cnt_out[i] = 0; g_cnt_in[i] = 0; g_mask[i] = -1; }
    if (i < BK)   { g_cnt2[i] = 0; }
}

// fused degree count + direct-bucket CSR-by-dst scatter
__global__ void __launch_bounds__(256) k_scatter1(const int* __restrict__ src,
                                                  const int* __restrict__ dst,
                                                  const float* __restrict__ ef) {
    int e = blockIdx.x * blockDim.x + threadIdx.x;
    if (e < ETOT) {
        int dn = dst[e], sn = src[e];
        atomicAdd(&g_cnt_out[sn], 1);
        int slot = atomicAdd(&g_cnt_in[dn], 1);
        if (slot < CAP) {
            g_csr_src[dn * CAP + slot] = sn;
            g_csr_val[dn * CAP + slot] = (sn != dn) ? ef[e] : 0.0f;  // e_feat*nonself
        }
    }
}

// correctly-rounded deg^-0.5 in f32 (via double)
__global__ void __launch_bounds__(256) k_deg() {
    int i = blockIdx.x * blockDim.x + threadIdx.x;
    if (i < NTOT) {
        double od = (double)max(g_cnt_out[i], 1);
        double id = (double)max(g_cnt_in[i], 1);
        g_sn[i] = (float)(1.0 / sqrt(od));
        g_dn[i] = (float)(1.0 / sqrt(id));
    }
}

// wa = W @ a in double (canonical) — one warp per output element
__global__ void __launch_bounds__(256) k_wa(const float* __restrict__ W,
                                            const float* __restrict__ a) {
    int warp = (blockIdx.x * blockDim.x + threadIdx.x) >> 5;
    int lane = threadIdx.x & 31;
    if (warp >= Dd) return;
    double s = 0.0;
    for (int k = lane; k < Dd; k += 32)
        s += (double)W[warp * Dd + k] * (double)a[k];
    #pragma unroll
    for (int o = 16; o; o >>= 1) s += __shfl_xor_sync(0xffffffffu, s, o);
    if (lane == 0) g_wa_d[warp] = s;
}

// fused: neighbor agg (double accum) + info in XLA row-reduce order + XLA sigmoid gate
__global__ void __launch_bounds__(256) k_node(const float* __restrict__ feat,
                                              float* __restrict__ out_xs) {
    int gw = (blockIdx.x * blockDim.x + threadIdx.x) >> 5;
    int lane = threadIdx.x & 31;
    if (gw >= NTOT) return;
    int node = gw;
    float2 fva = ((const float2*)(feat + (size_t)node * Dd))[lane];
    float2 fvb = ((const float2*)(feat + (size_t)node * Dd + 64))[lane];
    double a0 = 0.0, a1 = 0.0, a2 = 0.0, a3 = 0.0;
    int cnt = g_cnt_in[node]; if (cnt > CAP) cnt = CAP;
    int base = node * CAP;
    for (int p = 0; p < cnt; p++) {
        float v = g_csr_val[base + p];
        if (v != 0.f) {
            int s = g_csr_src[base + p];
            float sn = g_sn[s];
            float2 fsa = ((const float2*)(feat + (size_t)s * Dd))[lane];
            float2 fsb = ((const float2*)(feat + (size_t)s * Dd + 64))[lane];
            a0 += (double)((fsa.x * sn) * v);
            a1 += (double)((fsa.y * sn) * v);
            a2 += (double)((fsb.x * sn) * v);
            a3 += (double)((fsb.y * sn) * v);
        }
    }
    float dnf = g_dn[node];
    float g0 = (float)a0, g1 = (float)a1, g2v = (float)a2, g3 = (float)a3;
    float t0 = fabsf(fva.x - g0 * dnf);
    float t1 = fabsf(fva.y - g1 * dnf);
    float t2 = fabsf(fvb.x - g2v * dnf);
    float t3 = fabsf(fvb.y - g3 * dnf);
    float acc = ((t0 + t1) + t2) + t3;
    #pragma unroll
    for (int o = 16; o; o >>= 1)
        acc += __shfl_down_sync(0xffffffffu, acc, o);
    double dp_d = (double)fva.x * g_wa_d[2 * lane + 0]
                + (double)fva.y * g_wa_d[2 * lane + 1]
                + (double)fvb.x * g_wa_d[64 + 2 * lane + 0]
                + (double)fvb.y * g_wa_d[64 + 2 * lane + 1];
    #pragma unroll
    for (int o = 16; o; o >>= 1)
        dp_d += __shfl_xor_sync(0xffffffffu, dp_d, o);
    if (lane == 0) {
        float lr = (float)dp_d;
        float ll = (lr >= 0.f) ? lr : NEGS * lr;
        float t = tanh_xla(0.5f * ll);
        float attn = 0.5f * t + 0.5f;
        float sc = acc * attn;
        g_score[node] = sc;
        out_xs[node] = sc;
    }
}

// per-graph top-K via bitonic 1024 (desc by score, ties asc by index)
__global__ void __launch_bounds__(1024) k_topk(float* __restrict__ out_perm) {
    __shared__ float skey[Nn];
    __shared__ int   sidx[Nn];
    int b = blockIdx.x, tid = threadIdx.x;
    skey[tid] = g_score[b * Nn + tid];
    sidx[tid] = tid;
    __syncthreads();
    for (int k = 2; k <= Nn; k <<= 1) {
        for (int j = k >> 1; j > 0; j >>= 1) {
            int i = tid, ixj = i ^ j;
            if (ixj > i) {
                float ka = skey[i], kb = skey[ixj];
                int ia = sidx[i], ib = sidx[ixj];
                bool up = ((i & k) == 0);
                bool bBeforeA = (kb > ka) || (kb == ka && ib < ia);
                bool aBeforeB = (ka > kb) || (ka == kb && ia < ib);
                bool sw = up ? bBeforeA : aBeforeB;
                if (sw) { skey[i] = kb; skey[ixj] = ka; sidx[i] = ib; sidx[ixj] = ia; }
            }
            __syncthreads();
        }
    }
    if (tid < KP) {
        int node = b * Nn + sidx[tid];
        int p = b * KP + tid;
        g_pnode[p] = node;
        g_mask[node] = p;
        out_perm[p] = (float)node;
    }
}

// direct-bucket CSR of valid pooled edges, grouped by pooled column
__global__ void __launch_bounds__(256) k_scatter2(const int* __restrict__ src,
                                                  const int* __restrict__ dst,
                                                  const float* __restrict__ ef) {
    int e = blockIdx.x * blockDim.x + threadIdx.x;
    if (e < ETOT) {
        int nr = g_mask[src[e]], nc = g_mask[dst[e]];
        if (nr >= 0 && nc >= 0) {
            int slot = atomicAdd(&g_cnt2[nc], 1);
            if (slot < CAP) {
                g2_row[nc * CAP + slot] = nr % KP;
                g2_val[nc * CAP + slot] = LAMBDA * ef[e];
            }
        }
    }
}

__global__ void __launch_bounds__(256) k_pool(const float* __restrict__ feat,
                                              const float* __restrict__ att,
                                              float* __restrict__ out_fp) {
    int p = (blockIdx.x * blockDim.x + threadIdx.x) >> 5;
    int lane = threadIdx.x & 31;
    if (p >= BK) return;
    int node = g_pnode[p];
    float4 fv = ((const float4*)(feat + (size_t)node * Dd))[lane];
    ((float4*)(out_fp + (size_t)p * Dd))[lane] = fv;
    float4 a1 = ((const float4*)att)[lane];
    float4 a2 = ((const float4*)(att + Dd))[lane];
    double s1 = (double)fv.x * a1.x + (double)fv.y * a1.y
              + (double)fv.z * a1.z + (double)fv.w * a1.w;
    double s2 = (double)fv.x * a2.x + (double)fv.y * a2.y
              + (double)fv.z * a2.z + (double)fv.w * a2.w;
    for (int o = 16; o; o >>= 1) {
        s1 += __shfl_xor_sync(0xffffffffu, s1, o);
        s2 += __shfl_xor_sync(0xffffffffu, s2, o);
    }
    if (lane == 0) { g_wsrc[p] = (float)s1; g_wdst[p] = (float)s2; }
}

// fused Wblk build + edge adds + sparsemax (Michelot, f32, warm start) + transposed write
__global__ void __launch_bounds__(256) k_spm(float* __restrict__ out_w) {
    __shared__ float sh[KP * SHP];
    int b = blockIdx.y;
    int j0 = blockIdx.x * TJ;
    int ncols = KP - j0; if (ncols > TJ) ncols = TJ;
    int t = threadIdx.x;
    int w = t & (TJ - 1), iq = t >> 3;
    int wp = t >> 5, lane = t & 31;

    // phase 1: base scores leakyrelu(wsrc[i] + wdst[j])
    if (w < ncols) {
        float wdj = g_wdst[(size_t)b * KP + j0 + w];
        for (int i = iq; i < KP; i += 32) {
            float v = g_wsrc[b * KP + i] + wdj;
            sh[i * SHP + w] = (v >= 0.f) ? v : NEGS * v;
        }
    }
    __syncthreads();

    // phase 2: sparse edge additions (duplicates accumulate)
    if (wp < ncols) {
        int c = b * KP + j0 + wp;
        int cnt = g_cnt2[c]; if (cnt > CAP) cnt = CAP;
        int base = c * CAP;
        for (int e = lane; e < cnt; e += 32)
            atomicAdd(&sh[g2_row[base + e] * SHP + wp], g2_val[base + e]);
    }
    __syncthreads();

    // phase 3: sparsemax per column via Michelot (f32), warm start + robust break
    if (wp < ncols) {
        float z[NQ];
        #pragma unroll
        for (int q = 0; q < NQ; q++) {
            int i = q * 32 + lane;
            z[q] = (i < KP) ? sh[i * SHP + wp] : -1e30f;
        }
        float s = 0.f, zmax = -1e30f;
        #pragma unroll
        for (int q = 0; q < NQ; q++) {
            int i = q * 32 + lane;
            if (i < KP) s += z[q];
            zmax = fmaxf(zmax, z[q]);
        }
        #pragma unroll
        for (int o = 16; o; o >>= 1) {
            s += __shfl_xor_sync(0xffffffffu, s, o);
            zmax = fmaxf(zmax, __shfl_xor_sync(0xffffffffu, zmax, o));
        }
        // both are provable lower bounds on tau*: mean-based and (zmax - 1)
        float tau = fmaxf((s - 1.f) / (float)KP, zmax - 1.f);
        int kprev = 0x7fffffff;
        for (int it = 0; it < 60; it++) {
            float s2 = 0.f; int k2 = 0;
            #pragma unroll
            for (int q = 0; q < NQ; q++) {
                float zz = z[q];
                if (zz > tau) { s2 += zz; k2++; }
            }
            #pragma unroll
            for (int o = 16; o; o >>= 1) {
                s2 += __shfl_xor_sync(0xffffffffu, s2, o);
                k2 += __shfl_xor_sync(0xffffffffu, k2, o);
            }
            // support must strictly shrink; >= means converged or f32 oscillation
            if (k2 >= kprev || k2 == 0) break;
            float ntau = (s2 - 1.f) / (float)k2;
            if (ntau == tau) break;
            tau = ntau;
            kprev = k2;
        }
        #pragma unroll
        for (int q = 0; q < NQ; q++) {
            int i = q * 32 + lane;
            if (i < KP) {
                float d = z[q] - tau;
                sh[i * SHP + wp] = (d > 1e-9f) ? d : 0.f;
            }
        }
    }
    __syncthreads();

    // phase 4: coalesced transposed write: out[b][i][j]
    {
        size_t base = (size_t)b * KP * KP;
        int j = j0 + w;
        if (j < KP && w < ncols) {
            for (int i = iq; i < KP; i += 32)
                out_w[base + (size_t)i * KP + j] = sh[i * SHP + w];
        }
    }
}

extern "C" void kernel_launch(void* const* d_in, const int* in_sizes, int n_in,
                              void* d_out, int out_size) {
    const float* feat = (const float*)d_in[0];
    const float* ef   = (const float*)d_in[1];
    const float* W    = (const float*)d_in[2];
    const float* a    = (const float*)d_in[3];
    const float* att  = (const float*)d_in[4];
    const int*   src  = (const int*)d_in[5];
    const int*   dst  = (const int*)d_in[6];

    float* out      = (float*)d_out;
    float* out_fp   = out;                               // [BK, D]
    float* out_w    = out + (size_t)BK * Dd;             // [B, KP, KP]
    float* out_perm = out_w + (size_t)BK * KP;           // [BK]
    float* out_xs   = out_perm + BK;                     // [NTOT]

    k_init<<<(NTOT + 255) / 256, 256>>>();
    k_scatter1<<<(ETOT + 255) / 256, 256>>>(src, dst, ef);
    k_deg<<<(NTOT + 255) / 256, 256>>>();
    k_wa<<<(Dd * 32 + 255) / 256, 256>>>(W, a);
    k_node<<<(NTOT * 32 + 255) / 256, 256>>>(feat, out_xs);
    k_topk<<<Bg, 1024>>>(out_perm);
    k_scatter2<<<(ETOT + 255) / 256, 256>>>(src, dst, ef);
    k_pool<<<(BK * 32 + 255) / 256, 256>>>(feat, att, out_fp);

    dim3 g((KP + TJ - 1) / TJ, Bg);
    k_spm<<<g, 256>>>(out_w);
}